// round 15
// baseline (speedup 1.0000x reference)
#include <cuda_runtime.h>
#include <cstdint>

// ConcatenateMeanMax: out[b] = concat(bond_ft[b], mean(atom_ft[s0], atom_ft[s1]),
//                                     max(atom_ft[s0], atom_ft[s1]))
// DEG = 2 fixed (edge_dst is repeat(arange(n_bonds), 2)).
//
// R14 config (best measured: 155.7us ncu / 160.0us bench, 1.030GB @ 6.61TB/s):
// warp/bond, float4/lane, 1536B contiguous output rows, __ldcs bond,
// evict_last-policy-descriptor atom gathers, __stcs out.
// This round's single change: 1024-thread blocks (32 warps = 32 consecutive
// bonds = 48KB contiguous output per CTA) to improve DRAM write-burst page
// locality of the dominant 614MB store stream.

constexpr int D  = 128;
constexpr int DV = D / 4;  // 32 float4 per row

__device__ __forceinline__ float4 ldg_policy_v4(const float4* p, uint64_t pol) {
    float4 v;
    asm volatile("ld.global.nc.L2::cache_hint.v4.f32 {%0,%1,%2,%3}, [%4], %5;"
                 : "=f"(v.x), "=f"(v.y), "=f"(v.z), "=f"(v.w)
                 : "l"(p), "l"(pol));
    return v;
}

__global__ __launch_bounds__(1024)
void concat_mean_max_kernel(const float4* __restrict__ atom_ft,
                            const float4* __restrict__ bond_ft,
                            const int2*  __restrict__ edge_src2,
                            float4* __restrict__ out,
                            int n_bonds)
{
    const int gwarp = (blockIdx.x * blockDim.x + threadIdx.x) >> 5;
    const int lane  = threadIdx.x & 31;
    if (gwarp >= n_bonds) return;

    uint64_t pol;
    asm("createpolicy.fractional.L2::evict_last.b64 %0, 1.0;" : "=l"(pol));

    const int2 s = __ldg(&edge_src2[gwarp]);

    // read-once bond row: evict-first load
    const float4 bf = __ldcs(&bond_ft[(long long)gwarp * DV + lane]);

    // reused atom rows: evict_last policy descriptor
    const float4 a0 = ldg_policy_v4(&atom_ft[(long long)s.x * DV + lane], pol);
    const float4 a1 = ldg_policy_v4(&atom_ft[(long long)s.y * DV + lane], pol);

    float4 mean_v, max_v;
    mean_v.x = (a0.x + a1.x) * 0.5f;  max_v.x = fmaxf(a0.x, a1.x);
    mean_v.y = (a0.y + a1.y) * 0.5f;  max_v.y = fmaxf(a0.y, a1.y);
    mean_v.z = (a0.z + a1.z) * 0.5f;  max_v.z = fmaxf(a0.z, a1.z);
    mean_v.w = (a0.w + a1.w) * 0.5f;  max_v.w = fmaxf(a0.w, a1.w);

    float4* orow = out + (long long)gwarp * (3 * DV);
    // write-once output: streaming stores, contiguous 1536B per bond row,
    // 48KB contiguous per CTA
    __stcs(orow + lane,          bf);
    __stcs(orow + DV + lane,     mean_v);
    __stcs(orow + 2 * DV + lane, max_v);
}

extern "C" void kernel_launch(void* const* d_in, const int* in_sizes, int n_in,
                              void* d_out, int out_size)
{
    const float4* atom_ft  = (const float4*)d_in[0];   // [N_ATOMS, 128] f32
    const float4* bond_ft  = (const float4*)d_in[1];   // [N_BONDS, 128] f32
    const int2*   edge_src = (const int2*)d_in[2];     // [N_BONDS*2] i32 -> int2 per bond
    // d_in[3] = edge_dst (structurally repeat(arange, 2)) -- not needed.

    const int n_bonds = in_sizes[1] / D;

    const int threads = 1024;                // 32 warps/block -> 32 bonds/block
    const int warps_per_block = threads / 32;
    const int blocks = (n_bonds + warps_per_block - 1) / warps_per_block;

    concat_mean_max_kernel<<<blocks, threads>>>(
        atom_ft, bond_ft, edge_src, (float4*)d_out, n_bonds);
}

// round 16
// speedup vs baseline: 1.0170x; 1.0170x over previous
#include <cuda_runtime.h>
#include <cstdint>

// ConcatenateMeanMax: out[b] = concat(bond_ft[b], mean(atom_ft[s0], atom_ft[s1]),
//                                     max(atom_ft[s0], atom_ft[s1]))
// DEG = 2 fixed (edge_dst is repeat(arange(n_bonds), 2)).
//
// R14 body (best measured: 155.7us ncu / 160.0us bench, 1.030GB @ 6.61TB/s):
// warp/bond, float4/lane, 1536B contiguous output rows, __ldcs bond,
// evict_last-policy-descriptor atom gathers, __stcs out.
// Block-size sweep: 256 -> 81% occ / 6.61 TB/s; 1024 -> 70% occ / 6.49 TB/s.
// This round: the 512 midpoint (16 warps, 24KB contiguous output per CTA) --
// doubles store-burst span while keeping CTA quantization fine.

constexpr int D  = 128;
constexpr int DV = D / 4;  // 32 float4 per row

__device__ __forceinline__ float4 ldg_policy_v4(const float4* p, uint64_t pol) {
    float4 v;
    asm volatile("ld.global.nc.L2::cache_hint.v4.f32 {%0,%1,%2,%3}, [%4], %5;"
                 : "=f"(v.x), "=f"(v.y), "=f"(v.z), "=f"(v.w)
                 : "l"(p), "l"(pol));
    return v;
}

__global__ __launch_bounds__(512)
void concat_mean_max_kernel(const float4* __restrict__ atom_ft,
                            const float4* __restrict__ bond_ft,
                            const int2*  __restrict__ edge_src2,
                            float4* __restrict__ out,
                            int n_bonds)
{
    const int gwarp = (blockIdx.x * blockDim.x + threadIdx.x) >> 5;
    const int lane  = threadIdx.x & 31;
    if (gwarp >= n_bonds) return;

    uint64_t pol;
    asm("createpolicy.fractional.L2::evict_last.b64 %0, 1.0;" : "=l"(pol));

    const int2 s = __ldg(&edge_src2[gwarp]);

    // read-once bond row: evict-first load
    const float4 bf = __ldcs(&bond_ft[(long long)gwarp * DV + lane]);

    // reused atom rows: evict_last policy descriptor
    const float4 a0 = ldg_policy_v4(&atom_ft[(long long)s.x * DV + lane], pol);
    const float4 a1 = ldg_policy_v4(&atom_ft[(long long)s.y * DV + lane], pol);

    float4 mean_v, max_v;
    mean_v.x = (a0.x + a1.x) * 0.5f;  max_v.x = fmaxf(a0.x, a1.x);
    mean_v.y = (a0.y + a1.y) * 0.5f;  max_v.y = fmaxf(a0.y, a1.y);
    mean_v.z = (a0.z + a1.z) * 0.5f;  max_v.z = fmaxf(a0.z, a1.z);
    mean_v.w = (a0.w + a1.w) * 0.5f;  max_v.w = fmaxf(a0.w, a1.w);

    float4* orow = out + (long long)gwarp * (3 * DV);
    // write-once output: streaming stores, contiguous 1536B per bond row,
    // 24KB contiguous per CTA
    __stcs(orow + lane,          bf);
    __stcs(orow + DV + lane,     mean_v);
    __stcs(orow + 2 * DV + lane, max_v);
}

extern "C" void kernel_launch(void* const* d_in, const int* in_sizes, int n_in,
                              void* d_out, int out_size)
{
    const float4* atom_ft  = (const float4*)d_in[0];   // [N_ATOMS, 128] f32
    const float4* bond_ft  = (const float4*)d_in[1];   // [N_BONDS, 128] f32
    const int2*   edge_src = (const int2*)d_in[2];     // [N_BONDS*2] i32 -> int2 per bond
    // d_in[3] = edge_dst (structurally repeat(arange, 2)) -- not needed.

    const int n_bonds = in_sizes[1] / D;

    const int threads = 512;                 // 16 warps/block -> 16 bonds/block
    const int warps_per_block = threads / 32;
    const int blocks = (n_bonds + warps_per_block - 1) / warps_per_block;

    concat_mean_max_kernel<<<blocks, threads>>>(
        atom_ft, bond_ft, edge_src, (float4*)d_out, n_bonds);
}